// round 14
// baseline (speedup 1.0000x reference)
#include <cuda_runtime.h>
#include <math.h>

// Problem constants (from setup_inputs; p_sample=100 fixed)
#define Bn   512
#define Kd   256
#define KH   128
#define Gg   384     // 3*KH
#define Tt   101     // p_sample+1
#define Ff   16
#define MGX  (Bn*Tt) // 51712 = 808*64 exactly
#define GXB  (MGX/64)  // 808 gemm blocks along m
#define CPB  256       // extra x-blocks on k_gx (y0: copy, y1: enc)
#define GRUCP 20       // copy CTAs fused into k_gru
#define N4   ((long)Bn * Kd * 256 / 4)   // float4 count per passthrough tensor
#define NSPL ((N4 * 58) / 100)           // GRU-side copy share (58%)
#define GH8_BYTES (4 * 8 * Gg * 4)       // 49152 B dynamic smem for GRU partials

typedef unsigned long long ull;

// ---------------- packed fp32x2 helpers (sm_103a FFMA2) ----------------
__device__ __forceinline__ ull ff2(ull a, ull b, ull c) {
    ull d;
    asm("fma.rn.f32x2 %0, %1, %2, %3;" : "=l"(d) : "l"(a), "l"(b), "l"(c));
    return d;
}
__device__ __forceinline__ ull dup2(float x) {
    ull r; asm("mov.b64 %0, {%1, %1};" : "=l"(r) : "f"(x)); return r;
}
__device__ __forceinline__ float2 unpk2(ull v) {
    float2 r; asm("mov.b64 {%0, %1}, %2;" : "=f"(r.x), "=f"(r.y) : "l"(v)); return r;
}
__device__ __forceinline__ float fast_sigmoid(float x) {
    return 1.f / (1.f + __expf(-x));
}
__device__ __forceinline__ float fast_tanh(float x) {
    float e = __expf(2.f * x);
    return 1.f - 2.f / (e + 1.f);
}

// copy float4-sourced range [j0, j1) of both tensors; dst is float2 (8B aligned)
__device__ __forceinline__ void copy_range(const float4* __restrict__ a4,
                                           const float4* __restrict__ b4,
                                           float2* __restrict__ dst,
                                           long j0, long j1, long step) {
    const long o2 = 2 * N4;                   // float2 offset of second tensor
    for (long j = j0; j < j1; j += step) {
        float4 v = __ldg(&a4[j]);
        dst[2 * j]     = make_float2(v.x, v.y);
        dst[2 * j + 1] = make_float2(v.z, v.w);
        float4 w = __ldg(&b4[j]);
        dst[o2 + 2 * j]     = make_float2(w.x, w.y);
        dst[o2 + 2 * j + 1] = make_float2(w.z, w.w);
    }
}

// ---------------- scratch (device globals: allocation-free) ----------------
__device__ __align__(16) float g_gx[MGX * Gg];          // [m=b*101+t][g]
__device__ __align__(16) float g_WihT[Kd * Gg];         // [k][g]
__device__ __align__(16) float g_WkT[Ff * KH * Kd];     // [f][h][k]
__device__ __align__(16) float g_ctT[KH * Bn];          // [h][b]
__device__ __align__(16) float g_predT[Ff * Kd * Bn];   // [f][k][c]
__device__ __align__(16) float g_encT[Ff * Kd * Bn];    // [f][k][b]
__device__ __align__(16) float g_totals15[Bn * Bn];     // totals f=15 only
__device__ float g_partM[Ff * Bn * 4];   // per-(f,b,ctile) row max
__device__ float g_partS[Ff * Bn * 4];   // per-(f,b,ctile) sumexp
__device__ float g_diagv[Ff * Bn];       // totals[f][b][b]
__device__ float g_lse15[Bn];
__device__ float g_diag[Ff * Bn];
__device__ int   g_ok[Bn];

// ---------------- weight transposes (tiny) ----------------
__global__ void k_transpose_wih(const float* __restrict__ W) {
    int idx = blockIdx.x * 256 + threadIdx.x;           // 384*256
    if (idx < Gg * Kd) {
        int g = idx / Kd, k = idx % Kd;
        g_WihT[k * Gg + g] = W[idx];
    }
}
__global__ void k_transpose_wk(const float* __restrict__ W) {
    int idx = blockIdx.x * 256 + threadIdx.x;           // 16*256*128
    if (idx < Ff * Kd * KH) {
        int f = idx >> 15, r = idx & 32767, k = r >> 7, h = r & 127;
        g_WkT[f * (KH * Kd) + h * Kd + k] = W[idx];
    }
}

// ---------------- gx GEMM + fused copy (y0) + fused enc gather (y1) --------
__global__ __launch_bounds__(256) void k_gx(const float* __restrict__ z,
                                            const float* __restrict__ bih,
                                            const float4* __restrict__ cpA,
                                            const float4* __restrict__ cpB,
                                            float2* __restrict__ cpDst) {
    if (blockIdx.x >= GXB) {
        if (blockIdx.y == 0) {
            // gx-side share of passthrough copy (42%)
            long j0 = NSPL + (blockIdx.x - GXB) * 256L + threadIdx.x;
            copy_range(cpA, cpB, cpDst, j0, N4, (long)CPB * 256);
        } else if (blockIdx.y == 1) {
            // encoded gather: encT[f][k][b] = z[b][k][101+f]
            for (int idx = (blockIdx.x - GXB) * 256 + threadIdx.x;
                 idx < Ff * Kd * Bn; idx += CPB * 256) {
                int b = idx & 511, k = (idx >> 9) & 255, f = idx >> 17;
                g_encT[idx] = z[(size_t)b * (Kd * 256) + k * 256 + (Tt + f)];
            }
        }
        return;
    }

    __shared__ __align__(16) float As[32][64];
    __shared__ __align__(16) float Bs[32][128];
    int tid = threadIdx.x;
    int m0 = blockIdx.x * 64, n0 = blockIdx.y * 128;

    int mA = m0 + (tid & 63);
    int kA0 = tid >> 6;                       // 0..3
    int bq = mA / Tt, tq = mA - bq * Tt;      // fixed per thread
    const float* aptr = z + (size_t)bq * (Kd * 256) + tq;

    int nB = n0 + (tid & 127);
    int kB0 = tid >> 7;                       // 0..1
    int tx = tid & 31, ty = tid >> 5;

    ull acc[4][4];                             // [m-pair][n], packed along m
#pragma unroll
    for (int i = 0; i < 4; i++)
#pragma unroll
        for (int j = 0; j < 4; j++) acc[i][j] = 0ULL;

    for (int kt = 0; kt < Kd; kt += 32) {
#pragma unroll
        for (int i = 0; i < 8; i++) {
            int kl = kA0 + 4 * i;
            As[kl][tid & 63] = aptr[(size_t)(kt + kl) * 256];
        }
#pragma unroll
        for (int i = 0; i < 16; i++) {
            int kl = kB0 + 2 * i;
            Bs[kl][tid & 127] = g_WihT[(kt + kl) * Gg + nB];
        }
        __syncthreads();
#pragma unroll
        for (int k = 0; k < 32; k++) {
            ulonglong2 a0 = *(const ulonglong2*)&As[k][ty * 8];
            ulonglong2 a1 = *(const ulonglong2*)&As[k][ty * 8 + 4];
            float4 b4 = *(const float4*)&Bs[k][tx * 4];
            ull bb[4] = {dup2(b4.x), dup2(b4.y), dup2(b4.z), dup2(b4.w)};
            ull am[4] = {a0.x, a0.y, a1.x, a1.y};
#pragma unroll
            for (int i = 0; i < 4; i++)
#pragma unroll
                for (int j = 0; j < 4; j++) acc[i][j] = ff2(am[i], bb[j], acc[i][j]);
        }
        __syncthreads();
    }
    float4 bias = *(const float4*)&bih[n0 + tx * 4];
#pragma unroll
    for (int i = 0; i < 4; i++) {
        float2 c0 = unpk2(acc[i][0]), c1 = unpk2(acc[i][1]);
        float2 c2 = unpk2(acc[i][2]), c3 = unpk2(acc[i][3]);
        int mlo = m0 + ty * 8 + 2 * i;
        float4 vlo = {c0.x + bias.x, c1.x + bias.y, c2.x + bias.z, c3.x + bias.w};
        float4 vhi = {c0.y + bias.x, c1.y + bias.y, c2.y + bias.z, c3.y + bias.w};
        *(float4*)&g_gx[(size_t)mlo * Gg + n0 + tx * 4] = vlo;
        *(float4*)&g_gx[(size_t)(mlo + 1) * Gg + n0 + tx * 4] = vhi;
    }
}

// ---------------- persistent GRU v5: v4 + gx double-buffer prefetch --------
__global__ __launch_bounds__(768, 1) void k_gru(const float* __restrict__ h0,
                                                const float* __restrict__ Whh,
                                                const float* __restrict__ bhh,
                                                const float4* __restrict__ cpA,
                                                const float4* __restrict__ cpB,
                                                float2* __restrict__ cpDst) {
    if (blockIdx.x >= (Bn / 4)) {
        long j0 = (blockIdx.x - Bn / 4) * 768L + threadIdx.x;
        copy_range(cpA, cpB, cpDst, j0, NSPL, (long)GRUCP * 768);
        return;
    }

    extern __shared__ float gh8[];             // [4][8][Gg] partials
    __shared__ __align__(16) float h_sm[4][128];
    __shared__ float bh_sm[Gg];
    int tid = threadIdx.x;
    int b0 = blockIdx.x * 4;
    int g  = tid % 96;                         // gate base: owns g + 96*j
    int q  = tid / 96;                         // h-eighth in [0,8)

    ull w4[4][8];
#pragma unroll
    for (int j = 0; j < 4; j++) {
        const ulonglong2* wp = (const ulonglong2*)(Whh + (g + 96 * j) * KH + q * 16);
#pragma unroll
        for (int i = 0; i < 4; i++) {
            ulonglong2 v = wp[i];
            w4[j][2 * i] = v.x; w4[j][2 * i + 1] = v.y;
        }
    }

    if (tid < Gg) bh_sm[tid] = bhh[tid];
    int r2 = tid >> 7, j2 = tid & 127;         // valid for tid<512
    if (tid < 512) h_sm[r2][j2] = h0[(b0 + r2) * KH + j2];
    __syncthreads();

    const float* gp0 = g_gx + (size_t)(b0 + r2) * Tt * Gg;
    // preload step 0
    float xr = 0.f, xz = 0.f, xn = 0.f;
    if (tid < 512) {
        xr = gp0[j2]; xz = gp0[128 + j2]; xn = gp0[256 + j2];
    }
    for (int t = 0; t < Tt; t++) {
        // prefetch gx for step t+1 (full step of latency cover)
        float nxr = 0.f, nxz = 0.f, nxn = 0.f;
        if (tid < 512 && t + 1 < Tt) {
            const float* gp = gp0 + (size_t)(t + 1) * Gg;
            nxr = gp[j2]; nxz = gp[128 + j2]; nxn = gp[256 + j2];
        }
        // phase 1: per row, eighth-dot for FOUR gates off the same h loads
#pragma unroll
        for (int r = 0; r < 4; r++) {
            ull a0 = 0ULL, a1 = 0ULL, a2 = 0ULL, a3 = 0ULL;
            const ulonglong2* hp = (const ulonglong2*)&h_sm[r][q * 16];
#pragma unroll
            for (int i = 0; i < 4; i++) {
                ulonglong2 hv = hp[i];           // warp-uniform broadcast
                a0 = ff2(w4[0][2 * i], hv.x, a0); a0 = ff2(w4[0][2 * i + 1], hv.y, a0);
                a1 = ff2(w4[1][2 * i], hv.x, a1); a1 = ff2(w4[1][2 * i + 1], hv.y, a1);
                a2 = ff2(w4[2][2 * i], hv.x, a2); a2 = ff2(w4[2][2 * i + 1], hv.y, a2);
                a3 = ff2(w4[3][2 * i], hv.x, a3); a3 = ff2(w4[3][2 * i + 1], hv.y, a3);
            }
            float2 s0 = unpk2(a0), s1 = unpk2(a1), s2 = unpk2(a2), s3 = unpk2(a3);
            float* gr = gh8 + (r * 8 + q) * Gg + g;
            gr[0]   = s0.x + s0.y;
            gr[96]  = s1.x + s1.y;
            gr[192] = s2.x + s2.y;
            gr[288] = s3.x + s3.y;
        }
        __syncthreads();
        // phase 2: combine 8 eighths, gates + state update
        if (tid < 512) {
            const float* base = gh8 + (r2 * 8) * Gg;
            float hr = (((base[0 * Gg + j2] + base[1 * Gg + j2])
                       + (base[2 * Gg + j2] + base[3 * Gg + j2]))
                      + ((base[4 * Gg + j2] + base[5 * Gg + j2])
                       + (base[6 * Gg + j2] + base[7 * Gg + j2]))) + bh_sm[j2];
            int jz = 128 + j2;
            float hz = (((base[0 * Gg + jz] + base[1 * Gg + jz])
                       + (base[2 * Gg + jz] + base[3 * Gg + jz]))
                      + ((base[4 * Gg + jz] + base[5 * Gg + jz])
                       + (base[6 * Gg + jz] + base[7 * Gg + jz]))) + bh_sm[jz];
            int jn = 256 + j2;
            float hn = (((base[0 * Gg + jn] + base[1 * Gg + jn])
                       + (base[2 * Gg + jn] + base[3 * Gg + jn]))
                      + ((base[4 * Gg + jn] + base[5 * Gg + jn])
                       + (base[6 * Gg + jn] + base[7 * Gg + jn]))) + bh_sm[jn];
            float rr = fast_sigmoid(xr + hr);
            float zz = fast_sigmoid(xz + hz);
            float nn = fast_tanh(xn + rr * hn);
            float hp = h_sm[r2][j2];
            h_sm[r2][j2] = (1.f - zz) * nn + zz * hp;
        }
        __syncthreads();
        xr = nxr; xz = nxz; xn = nxn;
    }
    if (tid < 512) g_ctT[j2 * Bn + (b0 + r2)] = h_sm[r2][j2];
}

// ------------- generic batched GEMM (round-2 proven): C=sum_k A[k][m]B[k][n]
__global__ __launch_bounds__(256) void k_gemm(const float* __restrict__ A,
                                              const float* __restrict__ Bm,
                                              float* __restrict__ C,
                                              int lda, int ldb, int ldc, int KK,
                                              long sA, long sB, long sC,
                                              const float* __restrict__ rowBias, int sBias) {
    __shared__ __align__(16) float As[32][64];
    __shared__ __align__(16) float Bs[32][128];
    int f = blockIdx.z;
    A += (long)f * sA; Bm += (long)f * sB; C += (long)f * sC;
    int tid = threadIdx.x;
    int m0 = blockIdx.y * 64, n0 = blockIdx.x * 128;
    int mA = m0 + (tid & 63), kA0 = tid >> 6;
    int nB = n0 + (tid & 127), kB0 = tid >> 7;
    int tx = tid & 31, ty = tid >> 5;
    ull acc[4][4];
#pragma unroll
    for (int i = 0; i < 4; i++)
#pragma unroll
        for (int j = 0; j < 4; j++) acc[i][j] = 0ULL;

    for (int kt = 0; kt < KK; kt += 32) {
#pragma unroll
        for (int i = 0; i < 8; i++) { int kl = kA0 + 4 * i; As[kl][tid & 63] = A[(long)(kt + kl) * lda + mA]; }
#pragma unroll
        for (int i = 0; i < 16; i++) { int kl = kB0 + 2 * i; Bs[kl][tid & 127] = Bm[(long)(kt + kl) * ldb + nB]; }
        __syncthreads();
#pragma unroll
        for (int k = 0; k < 32; k++) {
            ulonglong2 a0 = *(const ulonglong2*)&As[k][ty * 8];
            ulonglong2 a1 = *(const ulonglong2*)&As[k][ty * 8 + 4];
            float4 b4 = *(const float4*)&Bs[k][tx * 4];
            ull bb[4] = {dup2(b4.x), dup2(b4.y), dup2(b4.z), dup2(b4.w)};
            ull am[4] = {a0.x, a0.y, a1.x, a1.y};
#pragma unroll
            for (int i = 0; i < 4; i++)
#pragma unroll
                for (int j = 0; j < 4; j++) acc[i][j] = ff2(am[i], bb[j], acc[i][j]);
        }
        __syncthreads();
    }
#pragma unroll
    for (int i = 0; i < 4; i++) {
        int mlo = m0 + ty * 8 + 2 * i;
        float blo = rowBias ? rowBias[(long)f * sBias + mlo] : 0.f;
        float bhi = rowBias ? rowBias[(long)f * sBias + mlo + 1] : 0.f;
        float2 c0 = unpk2(acc[i][0]), c1 = unpk2(acc[i][1]);
        float2 c2 = unpk2(acc[i][2]), c3 = unpk2(acc[i][3]);
        float4 vlo = {c0.x + blo, c1.x + blo, c2.x + blo, c3.x + blo};
        float4 vhi = {c0.y + bhi, c1.y + bhi, c2.y + bhi, c3.y + bhi};
        *(float4*)&C[(long)mlo * ldc + n0 + tx * 4] = vlo;
        *(float4*)&C[(long)(mlo + 1) * ldc + n0 + tx * 4] = vhi;
    }
}

// ---- totals GEMM with fused log-softmax partials ----
__global__ __launch_bounds__(256) void k_totals() {
    __shared__ __align__(16) float As[32][64];
    __shared__ __align__(16) float Bs[32][128];
    int f = blockIdx.z;
    const float* A  = g_encT  + (long)f * Kd * Bn;
    const float* Bm = g_predT + (long)f * Kd * Bn;
    int tid = threadIdx.x;
    int m0 = blockIdx.y * 64, n0 = blockIdx.x * 128;
    int mA = m0 + (tid & 63), kA0 = tid >> 6;
    int nB = n0 + (tid & 127), kB0 = tid >> 7;
    int tx = tid & 31, ty = tid >> 5;
    ull acc[4][4];
#pragma unroll
    for (int i = 0; i < 4; i++)
#pragma unroll
        for (int j = 0; j < 4; j++) acc[i][j] = 0ULL;

    for (int kt = 0; kt < Kd; kt += 32) {
#pragma unroll
        for (int i = 0; i < 8; i++) { int kl = kA0 + 4 * i; As[kl][tid & 63] = A[(long)(kt + kl) * Bn + mA]; }
#pragma unroll
        for (int i = 0; i < 16; i++) { int kl = kB0 + 2 * i; Bs[kl][tid & 127] = Bm[(long)(kt + kl) * Bn + nB]; }
        __syncthreads();
#pragma unroll
        for (int k = 0; k < 32; k++) {
            ulonglong2 a0 = *(const ulonglong2*)&As[k][ty * 8];
            ulonglong2 a1 = *(const ulonglong2*)&As[k][ty * 8 + 4];
            float4 b4 = *(const float4*)&Bs[k][tx * 4];
            ull bb[4] = {dup2(b4.x), dup2(b4.y), dup2(b4.z), dup2(b4.w)};
            ull am[4] = {a0.x, a0.y, a1.x, a1.y};
#pragma unroll
            for (int i = 0; i < 4; i++)
#pragma unroll
                for (int j = 0; j < 4; j++) acc[i][j] = ff2(am[i], bb[j], acc[i][j]);
        }
        __syncthreads();
    }
    float v[8][4];
#pragma unroll
    for (int i = 0; i < 4; i++) {
#pragma unroll
        for (int j = 0; j < 4; j++) {
            float2 c = unpk2(acc[i][j]);
            v[2 * i][j]     = c.x;
            v[2 * i + 1][j] = c.y;
        }
    }
    if (f == Ff - 1) {
#pragma unroll
        for (int i = 0; i < 8; i++) {
            int row = m0 + ty * 8 + i;
            *(float4*)&g_totals15[(long)row * Bn + n0 + tx * 4] =
                make_float4(v[i][0], v[i][1], v[i][2], v[i][3]);
        }
    }
#pragma unroll
    for (int i = 0; i < 8; i++) {
        int row = m0 + ty * 8 + i;
#pragma unroll
        for (int j = 0; j < 4; j++) {
            int col = n0 + tx * 4 + j;
            if (row == col) g_diagv[f * Bn + row] = v[i][j];
        }
    }
#pragma unroll
    for (int i = 0; i < 8; i++) {
        float lm = fmaxf(fmaxf(v[i][0], v[i][1]), fmaxf(v[i][2], v[i][3]));
#pragma unroll
        for (int s = 16; s; s >>= 1)
            lm = fmaxf(lm, __shfl_xor_sync(0xffffffffu, lm, s));
        float ls = __expf(v[i][0] - lm) + __expf(v[i][1] - lm)
                 + __expf(v[i][2] - lm) + __expf(v[i][3] - lm);
#pragma unroll
        for (int s = 16; s; s >>= 1)
            ls += __shfl_xor_sync(0xffffffffu, ls, s);
        if (tx == 0) {
            int row = m0 + ty * 8 + i;
            int idx = (f * Bn + row) * 4 + blockIdx.x;
            g_partM[idx] = lm;
            g_partS[idx] = ls;
        }
    }
}

// ---- combine partials: lse per (f,b); diag & lse15 outputs ----
__global__ void k_lse2() {
    int row = blockIdx.x * 256 + threadIdx.x;   // f*512 + b
    if (row >= Ff * Bn) return;
    const float* pm = g_partM + row * 4;
    const float* ps = g_partS + row * 4;
    float M = fmaxf(fmaxf(pm[0], pm[1]), fmaxf(pm[2], pm[3]));
    float S = ps[0] * expf(pm[0] - M) + ps[1] * expf(pm[1] - M)
            + ps[2] * expf(pm[2] - M) + ps[3] * expf(pm[3] - M);
    float lse = M + logf(S);
    g_diag[row] = g_diagv[row] - lse;
    if ((row >> 9) == Ff - 1) g_lse15[row & 511] = lse;
}

// ---------------- accuracy: argmax over b of softmax column ----------------
__global__ void k_acc() {
    int c = blockIdx.x;
    const float* p = g_totals15;
    int tid = threadIdx.x;                      // 128
    float best = -1e30f; int bi = 1 << 30;
    for (int b = tid; b < Bn; b += 128) {
        float v = p[(size_t)b * Bn + c] - g_lse15[b];
        if (v > best) { best = v; bi = b; }
    }
    __shared__ float sv[128]; __shared__ int si[128];
    sv[tid] = best; si[tid] = bi; __syncthreads();
    for (int s = 64; s; s >>= 1) {
        if (tid < s) {
            float v2 = sv[tid + s]; int i2 = si[tid + s];
            if (v2 > sv[tid] || (v2 == sv[tid] && i2 < si[tid])) { sv[tid] = v2; si[tid] = i2; }
        }
        __syncthreads();
    }
    if (tid == 0) g_ok[c] = (si[0] == c) ? 1 : 0;
}

// ---------------- deterministic final reduction -----------------------------
__global__ void k_final(float* __restrict__ out) {
    __shared__ float s[256]; __shared__ int si[256];
    int tid = threadIdx.x;
    float sum = 0.f;
    for (int i = tid; i < Ff * Bn; i += 256) sum += g_diag[i];
    int cnt = 0;
    for (int i = tid; i < Bn; i += 256) cnt += g_ok[i];
    s[tid] = sum; si[tid] = cnt; __syncthreads();
    for (int st = 128; st; st >>= 1) {
        if (tid < st) { s[tid] += s[tid + st]; si[tid] += si[tid + st]; }
        __syncthreads();
    }
    if (tid == 0) {
        out[0] = (float)si[0] / (float)Bn;               // accuracy
        out[1] = -s[0] / (float)(Ff * Bn);               // nce
    }
}

// ---------------- host ----------------
extern "C" void kernel_launch(void* const* d_in, const int* in_sizes, int n_in,
                              void* d_out, int out_size) {
    const float* zqst   = (const float*)d_in[0];
    const float* zex    = (const float*)d_in[1];
    const float* zqx    = (const float*)d_in[2];
    const float* hidden = (const float*)d_in[3];
    const float* Wih = (const float*)d_in[4];
    const float* Whh = (const float*)d_in[5];
    const float* bih = (const float*)d_in[6];
    const float* bhh = (const float*)d_in[7];
    const float* Wkw = (const float*)d_in[8];
    const float* Wkb = (const float*)d_in[9];
    float* out = (float*)d_out;

    float *p_wkT, *p_ctT, *p_predT;
    cudaGetSymbolAddress((void**)&p_wkT,   g_WkT);
    cudaGetSymbolAddress((void**)&p_ctT,   g_ctT);
    cudaGetSymbolAddress((void**)&p_predT, g_predT);

    cudaFuncSetAttribute(k_gru, cudaFuncAttributeMaxDynamicSharedMemorySize,
                         GH8_BYTES);

    // launch order keeps k_gru as the 4th launch (ncu captures it)
    k_transpose_wih<<<(Gg * Kd + 255) / 256, 256>>>(Wih);
    k_transpose_wk<<<(Ff * Kd * KH + 255) / 256, 256>>>(Wkw);

    // gx GEMM + 42% of copy (y0) + enc gather (y1)
    k_gx<<<dim3(GXB + CPB, Gg / 128), 256>>>(zqst, bih,
        (const float4*)zex, (const float4*)zqx, (float2*)(out + 2));

    // GRU v5 (gx prefetch) + 58% of copy on the 20 idle SMs
    k_gru<<<Bn / 4 + GRUCP, 768, GH8_BYTES>>>(hidden, Whh, bhh,
        (const float4*)zex, (const float4*)zqx, (float2*)(out + 2));

    // predT[f][k][c] = sum_h WkT[f][h][k] * ctT[h][c] + Wk_b[f][k]
    k_gemm<<<dim3(Bn / 128, Kd / 64, Ff), 256>>>(p_wkT, p_ctT, p_predT,
        Kd, Bn, Bn, KH, (long)KH * Kd, 0L, (long)Kd * Bn, Wkb, Kd);

    // totals GEMM with fused log-softmax partial reduction
    k_totals<<<dim3(Bn / 128, Bn / 64, Ff), 256>>>();

    k_lse2<<<(Ff * Bn + 255) / 256, 256>>>();
    k_acc<<<Bn, 128>>>();
    k_final<<<1, 256>>>(out);
}

// round 15
// speedup vs baseline: 1.6454x; 1.6454x over previous
#include <cuda_runtime.h>
#include <math.h>

// Problem constants (from setup_inputs; p_sample=100 fixed)
#define Bn   512
#define Kd   256
#define KH   128
#define Gg   384     // 3*KH
#define Tt   101     // p_sample+1
#define Ff   16
#define MGX  (Bn*Tt) // 51712 = 808*64 exactly
#define GXB  (MGX/64)  // 808 gemm blocks along m
#define CPB  256       // extra x-blocks on k_gx (y0: copy, y1: enc)
#define GRUCP 20       // copy CTAs fused into k_gru
#define N4   ((long)Bn * Kd * 256 / 4)   // float4 count per passthrough tensor
#define NSPL ((N4 * 58) / 100)           // GRU-side copy share (58%)
#define GH8_BYTES (4 * 8 * Gg * 4)       // 49152 B dynamic smem for GRU partials

typedef unsigned long long ull;

// ---------------- packed fp32x2 helpers (sm_103a FFMA2) ----------------
__device__ __forceinline__ ull ff2(ull a, ull b, ull c) {
    ull d;
    asm("fma.rn.f32x2 %0, %1, %2, %3;" : "=l"(d) : "l"(a), "l"(b), "l"(c));
    return d;
}
__device__ __forceinline__ ull dup2(float x) {
    ull r; asm("mov.b64 %0, {%1, %1};" : "=l"(r) : "f"(x)); return r;
}
__device__ __forceinline__ float2 unpk2(ull v) {
    float2 r; asm("mov.b64 {%0, %1}, %2;" : "=f"(r.x), "=f"(r.y) : "l"(v)); return r;
}
__device__ __forceinline__ float fast_sigmoid(float x) {
    return 1.f / (1.f + __expf(-x));
}
__device__ __forceinline__ float fast_tanh(float x) {
    float e = __expf(2.f * x);
    return 1.f - 2.f / (e + 1.f);
}

// copy float4-sourced range [j0, j1) of both tensors; dst is float2 (8B aligned)
__device__ __forceinline__ void copy_range(const float4* __restrict__ a4,
                                           const float4* __restrict__ b4,
                                           float2* __restrict__ dst,
                                           long j0, long j1, long step) {
    const long o2 = 2 * N4;                   // float2 offset of second tensor
    for (long j = j0; j < j1; j += step) {
        float4 v = __ldg(&a4[j]);
        dst[2 * j]     = make_float2(v.x, v.y);
        dst[2 * j + 1] = make_float2(v.z, v.w);
        float4 w = __ldg(&b4[j]);
        dst[o2 + 2 * j]     = make_float2(w.x, w.y);
        dst[o2 + 2 * j + 1] = make_float2(w.z, w.w);
    }
}

// ---------------- scratch (device globals: allocation-free) ----------------
__device__ __align__(16) float g_gx[MGX * Gg];          // [m=b*101+t][g]
__device__ __align__(16) float g_WihT[Kd * Gg];         // [k][g]
__device__ __align__(16) float g_WkT[Ff * KH * Kd];     // [f][h][k]
__device__ __align__(16) float g_ctT[KH * Bn];          // [h][b]
__device__ __align__(16) float g_predT[Ff * Kd * Bn];   // [f][k][c]
__device__ __align__(16) float g_encT[Ff * Kd * Bn];    // [f][k][b]
__device__ __align__(16) float g_totals15[Bn * Bn];     // totals f=15 only
__device__ float g_partM[Ff * Bn * 4];   // per-(f,b,ctile) row max
__device__ float g_partS[Ff * Bn * 4];   // per-(f,b,ctile) sumexp
__device__ float g_diagv[Ff * Bn];       // totals[f][b][b]
__device__ float g_lse15[Bn];
__device__ float g_diag[Ff * Bn];
__device__ int   g_ok[Bn];

// ---------------- weight transposes (tiny) ----------------
__global__ void k_transpose_wih(const float* __restrict__ W) {
    int idx = blockIdx.x * 256 + threadIdx.x;           // 384*256
    if (idx < Gg * Kd) {
        int g = idx / Kd, k = idx % Kd;
        g_WihT[k * Gg + g] = W[idx];
    }
}
__global__ void k_transpose_wk(const float* __restrict__ W) {
    int idx = blockIdx.x * 256 + threadIdx.x;           // 16*256*128
    if (idx < Ff * Kd * KH) {
        int f = idx >> 15, r = idx & 32767, k = r >> 7, h = r & 127;
        g_WkT[f * (KH * Kd) + h * Kd + k] = W[idx];
    }
}

// ---------------- gx GEMM + fused copy (y0) + fused enc gather (y1) --------
__global__ __launch_bounds__(256) void k_gx(const float* __restrict__ z,
                                            const float* __restrict__ bih,
                                            const float4* __restrict__ cpA,
                                            const float4* __restrict__ cpB,
                                            float2* __restrict__ cpDst) {
    if (blockIdx.x >= GXB) {
        if (blockIdx.y == 0) {
            // gx-side share of passthrough copy (42%)
            long j0 = NSPL + (blockIdx.x - GXB) * 256L + threadIdx.x;
            copy_range(cpA, cpB, cpDst, j0, N4, (long)CPB * 256);
        } else if (blockIdx.y == 1) {
            // encoded gather: encT[f][k][b] = z[b][k][101+f]
            for (int idx = (blockIdx.x - GXB) * 256 + threadIdx.x;
                 idx < Ff * Kd * Bn; idx += CPB * 256) {
                int b = idx & 511, k = (idx >> 9) & 255, f = idx >> 17;
                g_encT[idx] = z[(size_t)b * (Kd * 256) + k * 256 + (Tt + f)];
            }
        }
        return;
    }

    __shared__ __align__(16) float As[32][64];
    __shared__ __align__(16) float Bs[32][128];
    int tid = threadIdx.x;
    int m0 = blockIdx.x * 64, n0 = blockIdx.y * 128;

    int mA = m0 + (tid & 63);
    int kA0 = tid >> 6;                       // 0..3
    int bq = mA / Tt, tq = mA - bq * Tt;      // fixed per thread
    const float* aptr = z + (size_t)bq * (Kd * 256) + tq;

    int nB = n0 + (tid & 127);
    int kB0 = tid >> 7;                       // 0..1
    int tx = tid & 31, ty = tid >> 5;

    ull acc[4][4];                             // [m-pair][n], packed along m
#pragma unroll
    for (int i = 0; i < 4; i++)
#pragma unroll
        for (int j = 0; j < 4; j++) acc[i][j] = 0ULL;

    for (int kt = 0; kt < Kd; kt += 32) {
#pragma unroll
        for (int i = 0; i < 8; i++) {
            int kl = kA0 + 4 * i;
            As[kl][tid & 63] = aptr[(size_t)(kt + kl) * 256];
        }
#pragma unroll
        for (int i = 0; i < 16; i++) {
            int kl = kB0 + 2 * i;
            Bs[kl][tid & 127] = g_WihT[(kt + kl) * Gg + nB];
        }
        __syncthreads();
#pragma unroll
        for (int k = 0; k < 32; k++) {
            ulonglong2 a0 = *(const ulonglong2*)&As[k][ty * 8];
            ulonglong2 a1 = *(const ulonglong2*)&As[k][ty * 8 + 4];
            float4 b4 = *(const float4*)&Bs[k][tx * 4];
            ull bb[4] = {dup2(b4.x), dup2(b4.y), dup2(b4.z), dup2(b4.w)};
            ull am[4] = {a0.x, a0.y, a1.x, a1.y};
#pragma unroll
            for (int i = 0; i < 4; i++)
#pragma unroll
                for (int j = 0; j < 4; j++) acc[i][j] = ff2(am[i], bb[j], acc[i][j]);
        }
        __syncthreads();
    }
    float4 bias = *(const float4*)&bih[n0 + tx * 4];
#pragma unroll
    for (int i = 0; i < 4; i++) {
        float2 c0 = unpk2(acc[i][0]), c1 = unpk2(acc[i][1]);
        float2 c2 = unpk2(acc[i][2]), c3 = unpk2(acc[i][3]);
        int mlo = m0 + ty * 8 + 2 * i;
        float4 vlo = {c0.x + bias.x, c1.x + bias.y, c2.x + bias.z, c3.x + bias.w};
        float4 vhi = {c0.y + bias.x, c1.y + bias.y, c2.y + bias.z, c3.y + bias.w};
        *(float4*)&g_gx[(size_t)mlo * Gg + n0 + tx * 4] = vlo;
        *(float4*)&g_gx[(size_t)(mlo + 1) * Gg + n0 + tx * 4] = vhi;
    }
}

// ---------------- persistent GRU v4 (round-13 exact): gate-quads x eighths --
__global__ __launch_bounds__(768, 1) void k_gru(const float* __restrict__ h0,
                                                const float* __restrict__ Whh,
                                                const float* __restrict__ bhh,
                                                const float4* __restrict__ cpA,
                                                const float4* __restrict__ cpB,
                                                float2* __restrict__ cpDst) {
    if (blockIdx.x >= (Bn / 4)) {
        long j0 = (blockIdx.x - Bn / 4) * 768L + threadIdx.x;
        copy_range(cpA, cpB, cpDst, j0, NSPL, (long)GRUCP * 768);
        return;
    }

    extern __shared__ float gh8[];             // [4][8][Gg] partials
    __shared__ __align__(16) float h_sm[4][128];
    __shared__ float bh_sm[Gg];
    int tid = threadIdx.x;
    int b0 = blockIdx.x * 4;
    int g  = tid % 96;                         // gate base: owns g + 96*j
    int q  = tid / 96;                         // h-eighth in [0,8)

    ull w4[4][8];
#pragma unroll
    for (int j = 0; j < 4; j++) {
        const ulonglong2* wp = (const ulonglong2*)(Whh + (g + 96 * j) * KH + q * 16);
#pragma unroll
        for (int i = 0; i < 4; i++) {
            ulonglong2 v = wp[i];
            w4[j][2 * i] = v.x; w4[j][2 * i + 1] = v.y;
        }
    }

    if (tid < Gg) bh_sm[tid] = bhh[tid];
    int r2 = tid >> 7, j2 = tid & 127;         // valid for tid<512
    if (tid < 512) h_sm[r2][j2] = h0[(b0 + r2) * KH + j2];
    __syncthreads();

    const float* gp0 = g_gx + (size_t)(b0 + r2) * Tt * Gg;
    for (int t = 0; t < Tt; t++) {
        float xr = 0.f, xz = 0.f, xn = 0.f;
        if (tid < 512) {
            const float* gp = gp0 + (size_t)t * Gg;
            xr = gp[j2]; xz = gp[128 + j2]; xn = gp[256 + j2];
        }
#pragma unroll
        for (int r = 0; r < 4; r++) {
            ull a0 = 0ULL, a1 = 0ULL, a2 = 0ULL, a3 = 0ULL;
            const ulonglong2* hp = (const ulonglong2*)&h_sm[r][q * 16];
#pragma unroll
            for (int i = 0; i < 4; i++) {
                ulonglong2 hv = hp[i];           // warp-uniform broadcast
                a0 = ff2(w4[0][2 * i], hv.x, a0); a0 = ff2(w4[0][2 * i + 1], hv.y, a0);
                a1 = ff2(w4[1][2 * i], hv.x, a1); a1 = ff2(w4[1][2 * i + 1], hv.y, a1);
                a2 = ff2(w4[2][2 * i], hv.x, a2); a2 = ff2(w4[2][2 * i + 1], hv.y, a2);
                a3 = ff2(w4[3][2 * i], hv.x, a3); a3 = ff2(w4[3][2 * i + 1], hv.y, a3);
            }
            float2 s0 = unpk2(a0), s1 = unpk2(a1), s2 = unpk2(a2), s3 = unpk2(a3);
            float* gr = gh8 + (r * 8 + q) * Gg + g;
            gr[0]   = s0.x + s0.y;
            gr[96]  = s1.x + s1.y;
            gr[192] = s2.x + s2.y;
            gr[288] = s3.x + s3.y;
        }
        __syncthreads();
        if (tid < 512) {
            const float* base = gh8 + (r2 * 8) * Gg;
            float hr = (((base[0 * Gg + j2] + base[1 * Gg + j2])
                       + (base[2 * Gg + j2] + base[3 * Gg + j2]))
                      + ((base[4 * Gg + j2] + base[5 * Gg + j2])
                       + (base[6 * Gg + j2] + base[7 * Gg + j2]))) + bh_sm[j2];
            int jz = 128 + j2;
            float hz = (((base[0 * Gg + jz] + base[1 * Gg + jz])
                       + (base[2 * Gg + jz] + base[3 * Gg + jz]))
                      + ((base[4 * Gg + jz] + base[5 * Gg + jz])
                       + (base[6 * Gg + jz] + base[7 * Gg + jz]))) + bh_sm[jz];
            int jn = 256 + j2;
            float hn = (((base[0 * Gg + jn] + base[1 * Gg + jn])
                       + (base[2 * Gg + jn] + base[3 * Gg + jn]))
                      + ((base[4 * Gg + jn] + base[5 * Gg + jn])
                       + (base[6 * Gg + jn] + base[7 * Gg + jn]))) + bh_sm[jn];
            float rr = fast_sigmoid(xr + hr);
            float zz = fast_sigmoid(xz + hz);
            float nn = fast_tanh(xn + rr * hn);
            float hp = h_sm[r2][j2];
            h_sm[r2][j2] = (1.f - zz) * nn + zz * hp;
        }
        __syncthreads();
    }
    if (tid < 512) g_ctT[j2 * Bn + (b0 + r2)] = h_sm[r2][j2];
}

// ------------- generic batched GEMM (round-2 proven): C=sum_k A[k][m]B[k][n]
__global__ __launch_bounds__(256) void k_gemm(const float* __restrict__ A,
                                              const float* __restrict__ Bm,
                                              float* __restrict__ C,
                                              int lda, int ldb, int ldc, int KK,
                                              long sA, long sB, long sC,
                                              const float* __restrict__ rowBias, int sBias) {
    __shared__ __align__(16) float As[32][64];
    __shared__ __align__(16) float Bs[32][128];
    int f = blockIdx.z;
    A += (long)f * sA; Bm += (long)f * sB; C += (long)f * sC;
    int tid = threadIdx.x;
    int m0 = blockIdx.y * 64, n0 = blockIdx.x * 128;
    int mA = m0 + (tid & 63), kA0 = tid >> 6;
    int nB = n0 + (tid & 127), kB0 = tid >> 7;
    int tx = tid & 31, ty = tid >> 5;
    ull acc[4][4];
#pragma unroll
    for (int i = 0; i < 4; i++)
#pragma unroll
        for (int j = 0; j < 4; j++) acc[i][j] = 0ULL;

    for (int kt = 0; kt < KK; kt += 32) {
#pragma unroll
        for (int i = 0; i < 8; i++) { int kl = kA0 + 4 * i; As[kl][tid & 63] = A[(long)(kt + kl) * lda + mA]; }
#pragma unroll
        for (int i = 0; i < 16; i++) { int kl = kB0 + 2 * i; Bs[kl][tid & 127] = Bm[(long)(kt + kl) * ldb + nB]; }
        __syncthreads();
#pragma unroll
        for (int k = 0; k < 32; k++) {
            ulonglong2 a0 = *(const ulonglong2*)&As[k][ty * 8];
            ulonglong2 a1 = *(const ulonglong2*)&As[k][ty * 8 + 4];
            float4 b4 = *(const float4*)&Bs[k][tx * 4];
            ull bb[4] = {dup2(b4.x), dup2(b4.y), dup2(b4.z), dup2(b4.w)};
            ull am[4] = {a0.x, a0.y, a1.x, a1.y};
#pragma unroll
            for (int i = 0; i < 4; i++)
#pragma unroll
                for (int j = 0; j < 4; j++) acc[i][j] = ff2(am[i], bb[j], acc[i][j]);
        }
        __syncthreads();
    }
#pragma unroll
    for (int i = 0; i < 4; i++) {
        int mlo = m0 + ty * 8 + 2 * i;
        float blo = rowBias ? rowBias[(long)f * sBias + mlo] : 0.f;
        float bhi = rowBias ? rowBias[(long)f * sBias + mlo + 1] : 0.f;
        float2 c0 = unpk2(acc[i][0]), c1 = unpk2(acc[i][1]);
        float2 c2 = unpk2(acc[i][2]), c3 = unpk2(acc[i][3]);
        float4 vlo = {c0.x + blo, c1.x + blo, c2.x + blo, c3.x + blo};
        float4 vhi = {c0.y + bhi, c1.y + bhi, c2.y + bhi, c3.y + bhi};
        *(float4*)&C[(long)mlo * ldc + n0 + tx * 4] = vlo;
        *(float4*)&C[(long)(mlo + 1) * ldc + n0 + tx * 4] = vhi;
    }
}

// ---- totals GEMM with fused log-softmax partials ----
__global__ __launch_bounds__(256) void k_totals() {
    __shared__ __align__(16) float As[32][64];
    __shared__ __align__(16) float Bs[32][128];
    int f = blockIdx.z;
    const float* A  = g_encT  + (long)f * Kd * Bn;
    const float* Bm = g_predT + (long)f * Kd * Bn;
    int tid = threadIdx.x;
    int m0 = blockIdx.y * 64, n0 = blockIdx.x * 128;
    int mA = m0 + (tid & 63), kA0 = tid >> 6;
    int nB = n0 + (tid & 127), kB0 = tid >> 7;
    int tx = tid & 31, ty = tid >> 5;
    ull acc[4][4];
#pragma unroll
    for (int i = 0; i < 4; i++)
#pragma unroll
        for (int j = 0; j < 4; j++) acc[i][j] = 0ULL;

    for (int kt = 0; kt < Kd; kt += 32) {
#pragma unroll
        for (int i = 0; i < 8; i++) { int kl = kA0 + 4 * i; As[kl][tid & 63] = A[(long)(kt + kl) * Bn + mA]; }
#pragma unroll
        for (int i = 0; i < 16; i++) { int kl = kB0 + 2 * i; Bs[kl][tid & 127] = Bm[(long)(kt + kl) * Bn + nB]; }
        __syncthreads();
#pragma unroll
        for (int k = 0; k < 32; k++) {
            ulonglong2 a0 = *(const ulonglong2*)&As[k][ty * 8];
            ulonglong2 a1 = *(const ulonglong2*)&As[k][ty * 8 + 4];
            float4 b4 = *(const float4*)&Bs[k][tx * 4];
            ull bb[4] = {dup2(b4.x), dup2(b4.y), dup2(b4.z), dup2(b4.w)};
            ull am[4] = {a0.x, a0.y, a1.x, a1.y};
#pragma unroll
            for (int i = 0; i < 4; i++)
#pragma unroll
                for (int j = 0; j < 4; j++) acc[i][j] = ff2(am[i], bb[j], acc[i][j]);
        }
        __syncthreads();
    }
    float v[8][4];
#pragma unroll
    for (int i = 0; i < 4; i++) {
#pragma unroll
        for (int j = 0; j < 4; j++) {
            float2 c = unpk2(acc[i][j]);
            v[2 * i][j]     = c.x;
            v[2 * i + 1][j] = c.y;
        }
    }
    if (f == Ff - 1) {
#pragma unroll
        for (int i = 0; i < 8; i++) {
            int row = m0 + ty * 8 + i;
            *(float4*)&g_totals15[(long)row * Bn + n0 + tx * 4] =
                make_float4(v[i][0], v[i][1], v[i][2], v[i][3]);
        }
    }
#pragma unroll
    for (int i = 0; i < 8; i++) {
        int row = m0 + ty * 8 + i;
#pragma unroll
        for (int j = 0; j < 4; j++) {
            int col = n0 + tx * 4 + j;
            if (row == col) g_diagv[f * Bn + row] = v[i][j];
        }
    }
#pragma unroll
    for (int i = 0; i < 8; i++) {
        float lm = fmaxf(fmaxf(v[i][0], v[i][1]), fmaxf(v[i][2], v[i][3]));
#pragma unroll
        for (int s = 16; s; s >>= 1)
            lm = fmaxf(lm, __shfl_xor_sync(0xffffffffu, lm, s));
        float ls = __expf(v[i][0] - lm) + __expf(v[i][1] - lm)
                 + __expf(v[i][2] - lm) + __expf(v[i][3] - lm);
#pragma unroll
        for (int s = 16; s; s >>= 1)
            ls += __shfl_xor_sync(0xffffffffu, ls, s);
        if (tx == 0) {
            int row = m0 + ty * 8 + i;
            int idx = (f * Bn + row) * 4 + blockIdx.x;
            g_partM[idx] = lm;
            g_partS[idx] = ls;
        }
    }
}

// ---- combine partials: lse per (f,b); diag & lse15 outputs ----
__global__ void k_lse2() {
    int row = blockIdx.x * 256 + threadIdx.x;   // f*512 + b
    if (row >= Ff * Bn) return;
    const float* pm = g_partM + row * 4;
    const float* ps = g_partS + row * 4;
    float M = fmaxf(fmaxf(pm[0], pm[1]), fmaxf(pm[2], pm[3]));
    float S = ps[0] * expf(pm[0] - M) + ps[1] * expf(pm[1] - M)
            + ps[2] * expf(pm[2] - M) + ps[3] * expf(pm[3] - M);
    float lse = M + logf(S);
    g_diag[row] = g_diagv[row] - lse;
    if ((row >> 9) == Ff - 1) g_lse15[row & 511] = lse;
}

// ---------------- accuracy: argmax over b of softmax column ----------------
__global__ void k_acc() {
    int c = blockIdx.x;
    const float* p = g_totals15;
    int tid = threadIdx.x;                      // 128
    float best = -1e30f; int bi = 1 << 30;
    for (int b = tid; b < Bn; b += 128) {
        float v = p[(size_t)b * Bn + c] - g_lse15[b];
        if (v > best) { best = v; bi = b; }
    }
    __shared__ float sv[128]; __shared__ int si[128];
    sv[tid] = best; si[tid] = bi; __syncthreads();
    for (int s = 64; s; s >>= 1) {
        if (tid < s) {
            float v2 = sv[tid + s]; int i2 = si[tid + s];
            if (v2 > sv[tid] || (v2 == sv[tid] && i2 < si[tid])) { sv[tid] = v2; si[tid] = i2; }
        }
        __syncthreads();
    }
    if (tid == 0) g_ok[c] = (si[0] == c) ? 1 : 0;
}

// ---------------- deterministic final reduction -----------------------------
__global__ void k_final(float* __restrict__ out) {
    __shared__ float s[256]; __shared__ int si[256];
    int tid = threadIdx.x;
    float sum = 0.f;
    for (int i = tid; i < Ff * Bn; i += 256) sum += g_diag[i];
    int cnt = 0;
    for (int i = tid; i < Bn; i += 256) cnt += g_ok[i];
    s[tid] = sum; si[tid] = cnt; __syncthreads();
    for (int st = 128; st; st >>= 1) {
        if (tid < st) { s[tid] += s[tid + st]; si[tid] += si[tid + st]; }
        __syncthreads();
    }
    if (tid == 0) {
        out[0] = (float)si[0] / (float)Bn;               // accuracy
        out[1] = -s[0] / (float)(Ff * Bn);               // nce
    }
}

// ---------------- host ----------------
extern "C" void kernel_launch(void* const* d_in, const int* in_sizes, int n_in,
                              void* d_out, int out_size) {
    const float* zqst   = (const float*)d_in[0];
    const float* zex    = (const float*)d_in[1];
    const float* zqx    = (const float*)d_in[2];
    const float* hidden = (const float*)d_in[3];
    const float* Wih = (const float*)d_in[4];
    const float* Whh = (const float*)d_in[5];
    const float* bih = (const float*)d_in[6];
    const float* bhh = (const float*)d_in[7];
    const float* Wkw = (const float*)d_in[8];
    const float* Wkb = (const float*)d_in[9];
    float* out = (float*)d_out;

    float *p_wkT, *p_ctT, *p_predT;
    cudaGetSymbolAddress((void**)&p_wkT,   g_WkT);
    cudaGetSymbolAddress((void**)&p_ctT,   g_ctT);
    cudaGetSymbolAddress((void**)&p_predT, g_predT);

    cudaFuncSetAttribute(k_gru, cudaFuncAttributeMaxDynamicSharedMemorySize,
                         GH8_BYTES);

    // launch order keeps k_gru as the 4th launch (ncu captures it)
    k_transpose_wih<<<(Gg * Kd + 255) / 256, 256>>>(Wih);
    k_transpose_wk<<<(Ff * Kd * KH + 255) / 256, 256>>>(Wkw);

    // gx GEMM + 42% of copy (y0) + enc gather (y1)
    k_gx<<<dim3(GXB + CPB, Gg / 128), 256>>>(zqst, bih,
        (const float4*)zex, (const float4*)zqx, (float2*)(out + 2));

    // GRU v4 (round-13 exact) + 58% of copy on the 20 idle SMs
    k_gru<<<Bn / 4 + GRUCP, 768, GH8_BYTES>>>(hidden, Whh, bhh,
        (const float4*)zex, (const float4*)zqx, (float2*)(out + 2));

    // predT[f][k][c] = sum_h WkT[f][h][k] * ctT[h][c] + Wk_b[f][k]
    k_gemm<<<dim3(Bn / 128, Kd / 64, Ff), 256>>>(p_wkT, p_ctT, p_predT,
        Kd, Bn, Bn, KH, (long)KH * Kd, 0L, (long)Kd * Bn, Wkb, Kd);

    // totals GEMM with fused log-softmax partial reduction
    k_totals<<<dim3(Bn / 128, Bn / 64, Ff), 256>>>();

    k_lse2<<<(Ff * Bn + 255) / 256, 256>>>();
    k_acc<<<Bn, 128>>>();
    k_final<<<1, 256>>>(out);
}

// round 16
// speedup vs baseline: 1.7557x; 1.0670x over previous
#include <cuda_runtime.h>
#include <math.h>

// Problem constants (from setup_inputs; p_sample=100 fixed)
#define Bn   512
#define Kd   256
#define KH   128
#define Gg   384     // 3*KH
#define Tt   101     // p_sample+1
#define Ff   16
#define MGX  (Bn*Tt) // 51712 = 808*64 exactly
#define GXB  (MGX/64)  // 808 gemm blocks along m
#define CPB  256       // extra x-blocks on k_gx (y0: copy, y1: enc)
#define GRUCP 20       // copy CTAs fused into k_gru
#define N4   ((long)Bn * Kd * 256 / 4)   // float4 count per passthrough tensor
#define NSPL (N4 / 2)                    // GRU-side copy share (50% — measured knee)
#define GH8_BYTES (4 * 8 * Gg * 4)       // 49152 B dynamic smem for GRU partials
#define PREP_N (Gg * Kd + Ff * Kd * KH)  // merged transpose element count

typedef unsigned long long ull;

// ---------------- packed fp32x2 helpers (sm_103a FFMA2) ----------------
__device__ __forceinline__ ull ff2(ull a, ull b, ull c) {
    ull d;
    asm("fma.rn.f32x2 %0, %1, %2, %3;" : "=l"(d) : "l"(a), "l"(b), "l"(c));
    return d;
}
__device__ __forceinline__ ull dup2(float x) {
    ull r; asm("mov.b64 %0, {%1, %1};" : "=l"(r) : "f"(x)); return r;
}
__device__ __forceinline__ float2 unpk2(ull v) {
    float2 r; asm("mov.b64 {%0, %1}, %2;" : "=f"(r.x), "=f"(r.y) : "l"(v)); return r;
}
__device__ __forceinline__ float fast_sigmoid(float x) {
    return 1.f / (1.f + __expf(-x));
}
__device__ __forceinline__ float fast_tanh(float x) {
    float e = __expf(2.f * x);
    return 1.f - 2.f / (e + 1.f);
}

// copy float4-sourced range [j0, j1) of both tensors; dst is float2 (8B aligned)
__device__ __forceinline__ void copy_range(const float4* __restrict__ a4,
                                           const float4* __restrict__ b4,
                                           float2* __restrict__ dst,
                                           long j0, long j1, long step) {
    const long o2 = 2 * N4;                   // float2 offset of second tensor
    for (long j = j0; j < j1; j += step) {
        float4 v = __ldg(&a4[j]);
        dst[2 * j]     = make_float2(v.x, v.y);
        dst[2 * j + 1] = make_float2(v.z, v.w);
        float4 w = __ldg(&b4[j]);
        dst[o2 + 2 * j]     = make_float2(w.x, w.y);
        dst[o2 + 2 * j + 1] = make_float2(w.z, w.w);
    }
}

// ---------------- scratch (device globals: allocation-free) ----------------
__device__ __align__(16) float g_gx[MGX * Gg];          // [m=b*101+t][g]
__device__ __align__(16) float g_WihT[Kd * Gg];         // [k][g]
__device__ __align__(16) float g_WkT[Ff * KH * Kd];     // [f][h][k]
__device__ __align__(16) float g_ctT[KH * Bn];          // [h][b]
__device__ __align__(16) float g_predT[Ff * Kd * Bn];   // [f][k][c]
__device__ __align__(16) float g_encT[Ff * Kd * Bn];    // [f][k][b]
__device__ __align__(16) float g_totals15[Bn * Bn];     // totals f=15 only
__device__ float g_partM[Ff * Bn * 4];   // per-(f,b,ctile) row max
__device__ float g_partS[Ff * Bn * 4];   // per-(f,b,ctile) sumexp
__device__ float g_diagv[Ff * Bn];       // totals[f][b][b]
__device__ float g_lse15[Bn];
__device__ float g_diag[Ff * Bn];
__device__ int   g_ok[Bn];

// ---------------- merged weight transposes (one launch) ----------------
__global__ void k_prep(const float* __restrict__ Wih,
                       const float* __restrict__ Wk) {
    int idx = blockIdx.x * 256 + threadIdx.x;
    if (idx < Gg * Kd) {
        int g = idx / Kd, k = idx % Kd;
        g_WihT[k * Gg + g] = Wih[idx];
    } else if (idx < PREP_N) {
        int i2 = idx - Gg * Kd;                 // 16*256*128
        int f = i2 >> 15, r = i2 & 32767, k = r >> 7, h = r & 127;
        g_WkT[f * (KH * Kd) + h * Kd + k] = Wk[i2];
    }
}

// ---------------- gx GEMM + fused copy (y0) + fused enc gather (y1) --------
__global__ __launch_bounds__(256) void k_gx(const float* __restrict__ z,
                                            const float* __restrict__ bih,
                                            const float4* __restrict__ cpA,
                                            const float4* __restrict__ cpB,
                                            float2* __restrict__ cpDst) {
    if (blockIdx.x >= GXB) {
        if (blockIdx.y == 0) {
            // gx-side share of passthrough copy (50%)
            long j0 = NSPL + (blockIdx.x - GXB) * 256L + threadIdx.x;
            copy_range(cpA, cpB, cpDst, j0, N4, (long)CPB * 256);
        } else if (blockIdx.y == 1) {
            // encoded gather: encT[f][k][b] = z[b][k][101+f]
            for (int idx = (blockIdx.x - GXB) * 256 + threadIdx.x;
                 idx < Ff * Kd * Bn; idx += CPB * 256) {
                int b = idx & 511, k = (idx >> 9) & 255, f = idx >> 17;
                g_encT[idx] = z[(size_t)b * (Kd * 256) + k * 256 + (Tt + f)];
            }
        }
        return;
    }

    __shared__ __align__(16) float As[32][64];
    __shared__ __align__(16) float Bs[32][128];
    int tid = threadIdx.x;
    int m0 = blockIdx.x * 64, n0 = blockIdx.y * 128;

    int mA = m0 + (tid & 63);
    int kA0 = tid >> 6;                       // 0..3
    int bq = mA / Tt, tq = mA - bq * Tt;      // fixed per thread
    const float* aptr = z + (size_t)bq * (Kd * 256) + tq;

    int nB = n0 + (tid & 127);
    int kB0 = tid >> 7;                       // 0..1
    int tx = tid & 31, ty = tid >> 5;

    ull acc[4][4];                             // [m-pair][n], packed along m
#pragma unroll
    for (int i = 0; i < 4; i++)
#pragma unroll
        for (int j = 0; j < 4; j++) acc[i][j] = 0ULL;

    for (int kt = 0; kt < Kd; kt += 32) {
#pragma unroll
        for (int i = 0; i < 8; i++) {
            int kl = kA0 + 4 * i;
            As[kl][tid & 63] = aptr[(size_t)(kt + kl) * 256];
        }
#pragma unroll
        for (int i = 0; i < 16; i++) {
            int kl = kB0 + 2 * i;
            Bs[kl][tid & 127] = g_WihT[(kt + kl) * Gg + nB];
        }
        __syncthreads();
#pragma unroll
        for (int k = 0; k < 32; k++) {
            ulonglong2 a0 = *(const ulonglong2*)&As[k][ty * 8];
            ulonglong2 a1 = *(const ulonglong2*)&As[k][ty * 8 + 4];
            float4 b4 = *(const float4*)&Bs[k][tx * 4];
            ull bb[4] = {dup2(b4.x), dup2(b4.y), dup2(b4.z), dup2(b4.w)};
            ull am[4] = {a0.x, a0.y, a1.x, a1.y};
#pragma unroll
            for (int i = 0; i < 4; i++)
#pragma unroll
                for (int j = 0; j < 4; j++) acc[i][j] = ff2(am[i], bb[j], acc[i][j]);
        }
        __syncthreads();
    }
    float4 bias = *(const float4*)&bih[n0 + tx * 4];
#pragma unroll
    for (int i = 0; i < 4; i++) {
        float2 c0 = unpk2(acc[i][0]), c1 = unpk2(acc[i][1]);
        float2 c2 = unpk2(acc[i][2]), c3 = unpk2(acc[i][3]);
        int mlo = m0 + ty * 8 + 2 * i;
        float4 vlo = {c0.x + bias.x, c1.x + bias.y, c2.x + bias.z, c3.x + bias.w};
        float4 vhi = {c0.y + bias.x, c1.y + bias.y, c2.y + bias.z, c3.y + bias.w};
        *(float4*)&g_gx[(size_t)mlo * Gg + n0 + tx * 4] = vlo;
        *(float4*)&g_gx[(size_t)(mlo + 1) * Gg + n0 + tx * 4] = vhi;
    }
}

// ---------------- persistent GRU v4 (round-13 exact): gate-quads x eighths --
__global__ __launch_bounds__(768, 1) void k_gru(const float* __restrict__ h0,
                                                const float* __restrict__ Whh,
                                                const float* __restrict__ bhh,
                                                const float4* __restrict__ cpA,
                                                const float4* __restrict__ cpB,
                                                float2* __restrict__ cpDst) {
    if (blockIdx.x >= (Bn / 4)) {
        long j0 = (blockIdx.x - Bn / 4) * 768L + threadIdx.x;
        copy_range(cpA, cpB, cpDst, j0, NSPL, (long)GRUCP * 768);
        return;
    }

    extern __shared__ float gh8[];             // [4][8][Gg] partials
    __shared__ __align__(16) float h_sm[4][128];
    __shared__ float bh_sm[Gg];
    int tid = threadIdx.x;
    int b0 = blockIdx.x * 4;
    int g  = tid % 96;                         // gate base: owns g + 96*j
    int q  = tid / 96;                         // h-eighth in [0,8)

    ull w4[4][8];
#pragma unroll
    for (int j = 0; j < 4; j++) {
        const ulonglong2* wp = (const ulonglong2*)(Whh + (g + 96 * j) * KH + q * 16);
#pragma unroll
        for (int i = 0; i < 4; i++) {
            ulonglong2 v = wp[i];
            w4[j][2 * i] = v.x; w4[j][2 * i + 1] = v.y;
        }
    }

    if (tid < Gg) bh_sm[tid] = bhh[tid];
    int r2 = tid >> 7, j2 = tid & 127;         // valid for tid<512
    if (tid < 512) h_sm[r2][j2] = h0[(b0 + r2) * KH + j2];
    __syncthreads();

    const float* gp0 = g_gx + (size_t)(b0 + r2) * Tt * Gg;
    for (int t = 0; t < Tt; t++) {
        float xr = 0.f, xz = 0.f, xn = 0.f;
        if (tid < 512) {
            const float* gp = gp0 + (size_t)t * Gg;
            xr = gp[j2]; xz = gp[128 + j2]; xn = gp[256 + j2];
        }
#pragma unroll
        for (int r = 0; r < 4; r++) {
            ull a0 = 0ULL, a1 = 0ULL, a2 = 0ULL, a3 = 0ULL;
            const ulonglong2* hp = (const ulonglong2*)&h_sm[r][q * 16];
#pragma unroll
            for (int i = 0; i < 4; i++) {
                ulonglong2 hv = hp[i];           // warp-uniform broadcast
                a0 = ff2(w4[0][2 * i], hv.x, a0); a0 = ff2(w4[0][2 * i + 1], hv.y, a0);
                a1 = ff2(w4[1][2 * i], hv.x, a1); a1 = ff2(w4[1][2 * i + 1], hv.y, a1);
                a2 = ff2(w4[2][2 * i], hv.x, a2); a2 = ff2(w4[2][2 * i + 1], hv.y, a2);
                a3 = ff2(w4[3][2 * i], hv.x, a3); a3 = ff2(w4[3][2 * i + 1], hv.y, a3);
            }
            float2 s0 = unpk2(a0), s1 = unpk2(a1), s2 = unpk2(a2), s3 = unpk2(a3);
            float* gr = gh8 + (r * 8 + q) * Gg + g;
            gr[0]   = s0.x + s0.y;
            gr[96]  = s1.x + s1.y;
            gr[192] = s2.x + s2.y;
            gr[288] = s3.x + s3.y;
        }
        __syncthreads();
        if (tid < 512) {
            const float* base = gh8 + (r2 * 8) * Gg;
            float hr = (((base[0 * Gg + j2] + base[1 * Gg + j2])
                       + (base[2 * Gg + j2] + base[3 * Gg + j2]))
                      + ((base[4 * Gg + j2] + base[5 * Gg + j2])
                       + (base[6 * Gg + j2] + base[7 * Gg + j2]))) + bh_sm[j2];
            int jz = 128 + j2;
            float hz = (((base[0 * Gg + jz] + base[1 * Gg + jz])
                       + (base[2 * Gg + jz] + base[3 * Gg + jz]))
                      + ((base[4 * Gg + jz] + base[5 * Gg + jz])
                       + (base[6 * Gg + jz] + base[7 * Gg + jz]))) + bh_sm[jz];
            int jn = 256 + j2;
            float hn = (((base[0 * Gg + jn] + base[1 * Gg + jn])
                       + (base[2 * Gg + jn] + base[3 * Gg + jn]))
                      + ((base[4 * Gg + jn] + base[5 * Gg + jn])
                       + (base[6 * Gg + jn] + base[7 * Gg + jn]))) + bh_sm[jn];
            float rr = fast_sigmoid(xr + hr);
            float zz = fast_sigmoid(xz + hz);
            float nn = fast_tanh(xn + rr * hn);
            float hp = h_sm[r2][j2];
            h_sm[r2][j2] = (1.f - zz) * nn + zz * hp;
        }
        __syncthreads();
    }
    if (tid < 512) g_ctT[j2 * Bn + (b0 + r2)] = h_sm[r2][j2];
}

// ------------- generic batched GEMM (round-2 proven): C=sum_k A[k][m]B[k][n]
__global__ __launch_bounds__(256) void k_gemm(const float* __restrict__ A,
                                              const float* __restrict__ Bm,
                                              float* __restrict__ C,
                                              int lda, int ldb, int ldc, int KK,
                                              long sA, long sB, long sC,
                                              const float* __restrict__ rowBias, int sBias) {
    __shared__ __align__(16) float As[32][64];
    __shared__ __align__(16) float Bs[32][128];
    int f = blockIdx.z;
    A += (long)f * sA; Bm += (long)f * sB; C += (long)f * sC;
    int tid = threadIdx.x;
    int m0 = blockIdx.y * 64, n0 = blockIdx.x * 128;
    int mA = m0 + (tid & 63), kA0 = tid >> 6;
    int nB = n0 + (tid & 127), kB0 = tid >> 7;
    int tx = tid & 31, ty = tid >> 5;
    ull acc[4][4];
#pragma unroll
    for (int i = 0; i < 4; i++)
#pragma unroll
        for (int j = 0; j < 4; j++) acc[i][j] = 0ULL;

    for (int kt = 0; kt < KK; kt += 32) {
#pragma unroll
        for (int i = 0; i < 8; i++) { int kl = kA0 + 4 * i; As[kl][tid & 63] = A[(long)(kt + kl) * lda + mA]; }
#pragma unroll
        for (int i = 0; i < 16; i++) { int kl = kB0 + 2 * i; Bs[kl][tid & 127] = Bm[(long)(kt + kl) * ldb + nB]; }
        __syncthreads();
#pragma unroll
        for (int k = 0; k < 32; k++) {
            ulonglong2 a0 = *(const ulonglong2*)&As[k][ty * 8];
            ulonglong2 a1 = *(const ulonglong2*)&As[k][ty * 8 + 4];
            float4 b4 = *(const float4*)&Bs[k][tx * 4];
            ull bb[4] = {dup2(b4.x), dup2(b4.y), dup2(b4.z), dup2(b4.w)};
            ull am[4] = {a0.x, a0.y, a1.x, a1.y};
#pragma unroll
            for (int i = 0; i < 4; i++)
#pragma unroll
                for (int j = 0; j < 4; j++) acc[i][j] = ff2(am[i], bb[j], acc[i][j]);
        }
        __syncthreads();
    }
#pragma unroll
    for (int i = 0; i < 4; i++) {
        int mlo = m0 + ty * 8 + 2 * i;
        float blo = rowBias ? rowBias[(long)f * sBias + mlo] : 0.f;
        float bhi = rowBias ? rowBias[(long)f * sBias + mlo + 1] : 0.f;
        float2 c0 = unpk2(acc[i][0]), c1 = unpk2(acc[i][1]);
        float2 c2 = unpk2(acc[i][2]), c3 = unpk2(acc[i][3]);
        float4 vlo = {c0.x + blo, c1.x + blo, c2.x + blo, c3.x + blo};
        float4 vhi = {c0.y + bhi, c1.y + bhi, c2.y + bhi, c3.y + bhi};
        *(float4*)&C[(long)mlo * ldc + n0 + tx * 4] = vlo;
        *(float4*)&C[(long)(mlo + 1) * ldc + n0 + tx * 4] = vhi;
    }
}

// ---- totals GEMM with fused log-softmax partials ----
__global__ __launch_bounds__(256) void k_totals() {
    __shared__ __align__(16) float As[32][64];
    __shared__ __align__(16) float Bs[32][128];
    int f = blockIdx.z;
    const float* A  = g_encT  + (long)f * Kd * Bn;
    const float* Bm = g_predT + (long)f * Kd * Bn;
    int tid = threadIdx.x;
    int m0 = blockIdx.y * 64, n0 = blockIdx.x * 128;
    int mA = m0 + (tid & 63), kA0 = tid >> 6;
    int nB = n0 + (tid & 127), kB0 = tid >> 7;
    int tx = tid & 31, ty = tid >> 5;
    ull acc[4][4];
#pragma unroll
    for (int i = 0; i < 4; i++)
#pragma unroll
        for (int j = 0; j < 4; j++) acc[i][j] = 0ULL;

    for (int kt = 0; kt < Kd; kt += 32) {
#pragma unroll
        for (int i = 0; i < 8; i++) { int kl = kA0 + 4 * i; As[kl][tid & 63] = A[(long)(kt + kl) * Bn + mA]; }
#pragma unroll
        for (int i = 0; i < 16; i++) { int kl = kB0 + 2 * i; Bs[kl][tid & 127] = Bm[(long)(kt + kl) * Bn + nB]; }
        __syncthreads();
#pragma unroll
        for (int k = 0; k < 32; k++) {
            ulonglong2 a0 = *(const ulonglong2*)&As[k][ty * 8];
            ulonglong2 a1 = *(const ulonglong2*)&As[k][ty * 8 + 4];
            float4 b4 = *(const float4*)&Bs[k][tx * 4];
            ull bb[4] = {dup2(b4.x), dup2(b4.y), dup2(b4.z), dup2(b4.w)};
            ull am[4] = {a0.x, a0.y, a1.x, a1.y};
#pragma unroll
            for (int i = 0; i < 4; i++)
#pragma unroll
                for (int j = 0; j < 4; j++) acc[i][j] = ff2(am[i], bb[j], acc[i][j]);
        }
        __syncthreads();
    }
    float v[8][4];
#pragma unroll
    for (int i = 0; i < 4; i++) {
#pragma unroll
        for (int j = 0; j < 4; j++) {
            float2 c = unpk2(acc[i][j]);
            v[2 * i][j]     = c.x;
            v[2 * i + 1][j] = c.y;
        }
    }
    if (f == Ff - 1) {
#pragma unroll
        for (int i = 0; i < 8; i++) {
            int row = m0 + ty * 8 + i;
            *(float4*)&g_totals15[(long)row * Bn + n0 + tx * 4] =
                make_float4(v[i][0], v[i][1], v[i][2], v[i][3]);
        }
    }
#pragma unroll
    for (int i = 0; i < 8; i++) {
        int row = m0 + ty * 8 + i;
#pragma unroll
        for (int j = 0; j < 4; j++) {
            int col = n0 + tx * 4 + j;
            if (row == col) g_diagv[f * Bn + row] = v[i][j];
        }
    }
#pragma unroll
    for (int i = 0; i < 8; i++) {
        float lm = fmaxf(fmaxf(v[i][0], v[i][1]), fmaxf(v[i][2], v[i][3]));
#pragma unroll
        for (int s = 16; s; s >>= 1)
            lm = fmaxf(lm, __shfl_xor_sync(0xffffffffu, lm, s));
        float ls = __expf(v[i][0] - lm) + __expf(v[i][1] - lm)
                 + __expf(v[i][2] - lm) + __expf(v[i][3] - lm);
#pragma unroll
        for (int s = 16; s; s >>= 1)
            ls += __shfl_xor_sync(0xffffffffu, ls, s);
        if (tx == 0) {
            int row = m0 + ty * 8 + i;
            int idx = (f * Bn + row) * 4 + blockIdx.x;
            g_partM[idx] = lm;
            g_partS[idx] = ls;
        }
    }
}

// ---- combine partials: lse per (f,b); diag & lse15 outputs ----
__global__ void k_lse2() {
    int row = blockIdx.x * 256 + threadIdx.x;   // f*512 + b
    if (row >= Ff * Bn) return;
    const float* pm = g_partM + row * 4;
    const float* ps = g_partS + row * 4;
    float M = fmaxf(fmaxf(pm[0], pm[1]), fmaxf(pm[2], pm[3]));
    float S = ps[0] * expf(pm[0] - M) + ps[1] * expf(pm[1] - M)
            + ps[2] * expf(pm[2] - M) + ps[3] * expf(pm[3] - M);
    float lse = M + logf(S);
    g_diag[row] = g_diagv[row] - lse;
    if ((row >> 9) == Ff - 1) g_lse15[row & 511] = lse;
}

// ---------------- accuracy: argmax over b of softmax column ----------------
__global__ void k_acc() {
    int c = blockIdx.x;
    const float* p = g_totals15;
    int tid = threadIdx.x;                      // 128
    float best = -1e30f; int bi = 1 << 30;
    for (int b = tid; b < Bn; b += 128) {
        float v = p[(size_t)b * Bn + c] - g_lse15[b];
        if (v > best) { best = v; bi = b; }
    }
    __shared__ float sv[128]; __shared__ int si[128];
    sv[tid] = best; si[tid] = bi; __syncthreads();
    for (int s = 64; s; s >>= 1) {
        if (tid < s) {
            float v2 = sv[tid + s]; int i2 = si[tid + s];
            if (v2 > sv[tid] || (v2 == sv[tid] && i2 < si[tid])) { sv[tid] = v2; si[tid] = i2; }
        }
        __syncthreads();
    }
    if (tid == 0) g_ok[c] = (si[0] == c) ? 1 : 0;
}

// ---------------- deterministic final reduction -----------------------------
__global__ void k_final(float* __restrict__ out) {
    __shared__ float s[256]; __shared__ int si[256];
    int tid = threadIdx.x;
    float sum = 0.f;
    for (int i = tid; i < Ff * Bn; i += 256) sum += g_diag[i];
    int cnt = 0;
    for (int i = tid; i < Bn; i += 256) cnt += g_ok[i];
    s[tid] = sum; si[tid] = cnt; __syncthreads();
    for (int st = 128; st; st >>= 1) {
        if (tid < st) { s[tid] += s[tid + st]; si[tid] += si[tid + st]; }
        __syncthreads();
    }
    if (tid == 0) {
        out[0] = (float)si[0] / (float)Bn;               // accuracy
        out[1] = -s[0] / (float)(Ff * Bn);               // nce
    }
}

// ---------------- host ----------------
extern "C" void kernel_launch(void* const* d_in, const int* in_sizes, int n_in,
                              void* d_out, int out_size) {
    const float* zqst   = (const float*)d_in[0];
    const float* zex    = (const float*)d_in[1];
    const float* zqx    = (const float*)d_in[2];
    const float* hidden = (const float*)d_in[3];
    const float* Wih = (const float*)d_in[4];
    const float* Whh = (const float*)d_in[5];
    const float* bih = (const float*)d_in[6];
    const float* bhh = (const float*)d_in[7];
    const float* Wkw = (const float*)d_in[8];
    const float* Wkb = (const float*)d_in[9];
    float* out = (float*)d_out;

    float *p_wkT, *p_ctT, *p_predT;
    cudaGetSymbolAddress((void**)&p_wkT,   g_WkT);
    cudaGetSymbolAddress((void**)&p_ctT,   g_ctT);
    cudaGetSymbolAddress((void**)&p_predT, g_predT);

    cudaFuncSetAttribute(k_gru, cudaFuncAttributeMaxDynamicSharedMemorySize,
                         GH8_BYTES);

    // merged weight transposes (one launch)
    k_prep<<<(PREP_N + 255) / 256, 256>>>(Wih, Wkw);

    // gx GEMM + 50% of copy (y0) + enc gather (y1)
    k_gx<<<dim3(GXB + CPB, Gg / 128), 256>>>(zqst, bih,
        (const float4*)zex, (const float4*)zqx, (float2*)(out + 2));

    // GRU v4 + 50% of copy on the 20 idle SMs (measured knee)
    k_gru<<<Bn / 4 + GRUCP, 768, GH8_BYTES>>>(hidden, Whh, bhh,
        (const float4*)zex, (const float4*)zqx, (float2*)(out + 2));

    // predT[f][k][c] = sum_h WkT[f][h][k] * ctT[h][c] + Wk_b[f][k]
    k_gemm<<<dim3(Bn / 128, Kd / 64, Ff), 256>>>(p_wkT, p_ctT, p_predT,
        Kd, Bn, Bn, KH, (long)KH * Kd, 0L, (long)Kd * Bn, Wkb, Kd);

    // totals GEMM with fused log-softmax partial reduction
    k_totals<<<dim3(Bn / 128, Bn / 64, Ff), 256>>>();

    k_lse2<<<(Ff * Bn + 255) / 256, 256>>>();
    k_acc<<<Bn, 128>>>();
    k_final<<<1, 256>>>(out);
}